// round 16
// baseline (speedup 1.0000x reference)
#include <cuda_runtime.h>
#include <cuda_fp16.h>
#include <cstddef>

// GCN 2-layer: CSR build (ticket scan) + gather aggregation, fp16 messages,
// software-pipelined layer-1 GEMM. N=100000, E=3.2M, 128->32->2. edges int32.

static constexpr int NMAX  = 100000;
static constexpr long long EMAX = 3300000;
static constexpr int D_IN  = 128;
static constexpr int D_H   = 32;
static constexpr int D_OUT = 2;
static constexpr int SCAN_BLK = 2048;
static constexpr int GEMM_BLOCKS = 592;     // 4/SM x 148

__device__ __align__(16) float  g_dinv[NMAX];
__device__ __align__(16) __half g_m1h [(size_t)NMAX * D_H];  // (x@W1)*dinv, fp16
__device__ __align__(16) float  g_p2  [(size_t)NMAX * D_OUT];
__device__ __align__(16) int    g_cnt[NMAX];
__device__ __align__(16) int    g_off[NMAX];    // exclusive start -> END after fill
__device__ int g_adj[EMAX];
__device__ int g_total;

// ---- P0: zero counts (int4) + ticket ----------------------------------------
__global__ void k_zero(int n4) {
    int i = blockIdx.x * blockDim.x + threadIdx.x;
    if (i < n4) ((int4*)g_cnt)[i] = make_int4(0, 0, 0, 0);
    if (i == 0) g_total = 0;
}

// ---- P1: count degrees (int4) ----------------------------------------------
__global__ void k_count(const int* __restrict__ dst, int E) {
    int i = blockIdx.x * blockDim.x + threadIdx.x;
    int e = i * 4;
    if (e + 3 < E) {
        int4 d = *(const int4*)(dst + e);
        atomicAdd(&g_cnt[d.x], 1);
        atomicAdd(&g_cnt[d.y], 1);
        atomicAdd(&g_cnt[d.z], 1);
        atomicAdd(&g_cnt[d.w], 1);
    } else {
        for (; e < E; e++) atomicAdd(&g_cnt[dst[e]], 1);
    }
}

// ---- P2: block-local scan + atomic ticket for region base + dinv -----------
__global__ void __launch_bounds__(256) k_scanoff(int n) {
    __shared__ int sp[256];
    __shared__ int sbase;
    int tid = threadIdx.x;
    int base = blockIdx.x * SCAN_BLK + tid * 8;
    int v[8]; int s = 0;
    #pragma unroll
    for (int j = 0; j < 8; j++) {
        int i = base + j;
        v[j] = (i < n) ? g_cnt[i] : 0;
        s += v[j];
    }
    sp[tid] = s; __syncthreads();
    for (int o = 1; o < 256; o <<= 1) {
        int t = (tid >= o) ? sp[tid - o] : 0;
        __syncthreads();
        sp[tid] += t;
        __syncthreads();
    }
    if (tid == 255) sbase = atomicAdd(&g_total, sp[255]);   // claim region
    __syncthreads();
    int excl = sbase + sp[tid] - s;
    #pragma unroll
    for (int j = 0; j < 8; j++) {
        int i = base + j;
        if (i < n) {
            g_off[i]  = excl; excl += v[j];
            g_dinv[i] = rsqrtf((float)v[j] + 1.0f);   // +1 self loop
        }
    }
}

// ---- P3: CSR fill (no smem, high occupancy) ---------------------------------
__global__ void k_fill(const int* __restrict__ src, const int* __restrict__ dst, int E) {
    int e = blockIdx.x * blockDim.x + threadIdx.x;
    if (e >= E) return;
    int d = dst[e];
    int pos = atomicAdd(&g_off[d], 1);          // g_off -> END pointer
    g_adj[pos] = src[e];
}

// ---- P4: pipelined layer-1 GEMM: m1h = fp16((x@W1)*dinv) --------------------
// 8 warps x 4 rows = 32-row tiles, grid-stride with register prefetch:
// next tile's x is in flight (4x LDG.128/thread) while computing current.
__global__ void __launch_bounds__(256) k_gemm1(const float* __restrict__ x,
                                               const float* __restrict__ W1,
                                               int n, int nblk) {
    __shared__ float  sWp[D_IN * D_H];          // 16 KB, k-pair interleaved W1^T
    __shared__ float4 sx[8][4][D_IN / 4];       // 16 KB: [warp][row][k4]
    int tid = threadIdx.x;
    for (int i = tid; i < D_IN * D_H; i += 256) {
        int k = i >> 5, c = i & 31;
        sWp[(k >> 1) * 64 + c * 2 + (k & 1)] = W1[i];
    }
    int warp = tid >> 5, lane = tid & 31;
    int ntile = (n + 31) >> 5;

    float4 pf[4];
    int tile = blockIdx.x;
    if (tile < ntile) {                          // prologue load
        int row0 = tile * 32 + warp * 4;
        #pragma unroll
        for (int r = 0; r < 4; r++) {
            int row = row0 + r;
            pf[r] = (row < n) ? ((const float4*)(x + (size_t)row * D_IN))[lane]
                              : make_float4(0.f, 0.f, 0.f, 0.f);
        }
    }
    for (; tile < ntile; tile += nblk) {
        __syncthreads();                         // prev compute done (+ W ready)
        #pragma unroll
        for (int r = 0; r < 4; r++) sx[warp][r][lane] = pf[r];
        __syncthreads();
        int next = tile + nblk;
        if (next < ntile) {                      // prefetch next tile
            int row0n = next * 32 + warp * 4;
            #pragma unroll
            for (int r = 0; r < 4; r++) {
                int row = row0n + r;
                pf[r] = (row < n) ? ((const float4*)(x + (size_t)row * D_IN))[lane]
                                  : make_float4(0.f, 0.f, 0.f, 0.f);
            }
        }
        const ulonglong2* sxp = (const ulonglong2*)&sx[warp][0][0];
        const unsigned long long* sWq = (const unsigned long long*)sWp;
        unsigned long long acc[4] = {0ull, 0ull, 0ull, 0ull};
        #pragma unroll 4
        for (int k4 = 0; k4 < D_IN / 4; k4++) {
            unsigned long long w01 = sWq[(k4 * 2 + 0) * 32 + lane];
            unsigned long long w23 = sWq[(k4 * 2 + 1) * 32 + lane];
            #pragma unroll
            for (int r = 0; r < 4; r++) {
                ulonglong2 xp = sxp[r * 32 + k4];
                asm("fma.rn.f32x2 %0, %1, %2, %0;" : "+l"(acc[r]) : "l"(xp.x), "l"(w01));
                asm("fma.rn.f32x2 %0, %1, %2, %0;" : "+l"(acc[r]) : "l"(xp.y), "l"(w23));
            }
        }
        int row0 = tile * 32 + warp * 4;
        #pragma unroll
        for (int r = 0; r < 4; r++) {
            int row = row0 + r;
            if (row < n) {
                float lo = __uint_as_float((unsigned)(acc[r] & 0xffffffffull));
                float hi = __uint_as_float((unsigned)(acc[r] >> 32));
                g_m1h[(size_t)row * D_H + lane] =
                    __float2half_rn((lo + hi) * g_dinv[row]);
            }
        }
    }
}

// ---- P5: fused layer-1 gather (fp16 msgs) + layer-2 transform ---------------
__global__ void __launch_bounds__(256) k_gather1(const float* __restrict__ b1,
                                                 const float* __restrict__ W2,
                                                 const float* __restrict__ b2,
                                                 float* __restrict__ out, int n) {
    int w = (int)((blockIdx.x * 256 + threadIdx.x) >> 5);
    int lane = threadIdx.x & 31;
    if (w >= n) return;
    int cnt = g_cnt[w];
    int start = g_off[w] - cnt;                 // off is END after fill
    float dv = g_dinv[w];

    float a0 = 0.f, a1 = 0.f, a2 = 0.f, a3 = 0.f;
    int j = 0;
    for (; j + 32 <= cnt; j += 32) {
        int idx = g_adj[start + j + lane];
        #pragma unroll
        for (int t = 0; t < 32; t += 4) {
            int s0 = __shfl_sync(0xffffffffu, idx, t + 0);
            int s1 = __shfl_sync(0xffffffffu, idx, t + 1);
            int s2 = __shfl_sync(0xffffffffu, idx, t + 2);
            int s3 = __shfl_sync(0xffffffffu, idx, t + 3);
            a0 += __half2float(g_m1h[(size_t)s0 * D_H + lane]);
            a1 += __half2float(g_m1h[(size_t)s1 * D_H + lane]);
            a2 += __half2float(g_m1h[(size_t)s2 * D_H + lane]);
            a3 += __half2float(g_m1h[(size_t)s3 * D_H + lane]);
        }
    }
    if (j < cnt) {
        int rem = cnt - j;
        int idx = (lane < rem) ? g_adj[start + j + lane] : 0;
        for (int t = 0; t < rem; t++) {
            int s = __shfl_sync(0xffffffffu, idx, t);
            a0 += __half2float(g_m1h[(size_t)s * D_H + lane]);
        }
    }
    float acc = (a0 + a1) + (a2 + a3);
    acc += __half2float(g_m1h[(size_t)w * D_H + lane]);   // self loop
    float h = fmaxf(acc * dv + __ldg(&b1[lane]), 0.f);
    float p0 = h * __ldg(&W2[lane * 2 + 0]);
    float p1 = h * __ldg(&W2[lane * 2 + 1]);
    #pragma unroll
    for (int o = 16; o; o >>= 1) {
        p0 += __shfl_xor_sync(0xffffffffu, p0, o);
        p1 += __shfl_xor_sync(0xffffffffu, p1, o);
    }
    if (lane == 0) {
        float q0 = p0 * dv, q1 = p1 * dv;
        g_p2[(size_t)w * 2 + 0] = q0;
        g_p2[(size_t)w * 2 + 1] = q1;
        out[(size_t)w * 2 + 0] = __ldg(&b2[0]) + q0 * dv;   // bias + self loop
        out[(size_t)w * 2 + 1] = __ldg(&b2[1]) + q1 * dv;
    }
}

// ---- P6: layer-2 gather ------------------------------------------------------
__global__ void __launch_bounds__(256) k_gather2(float* __restrict__ out, int n) {
    int w = (int)((blockIdx.x * 256 + threadIdx.x) >> 5);
    int lane = threadIdx.x & 31;
    if (w >= n) return;
    int cnt = g_cnt[w];
    int start = g_off[w] - cnt;
    float a0 = 0.f, a1 = 0.f;
    for (int j = lane; j < cnt; j += 32) {
        int s = g_adj[start + j];
        float2 p = *(const float2*)(g_p2 + (size_t)s * 2);
        a0 += p.x; a1 += p.y;
    }
    #pragma unroll
    for (int o = 16; o; o >>= 1) {
        a0 += __shfl_xor_sync(0xffffffffu, a0, o);
        a1 += __shfl_xor_sync(0xffffffffu, a1, o);
    }
    if (lane == 0) {
        float dv = g_dinv[w];
        out[(size_t)w * 2 + 0] += a0 * dv;
        out[(size_t)w * 2 + 1] += a1 * dv;
    }
}

extern "C" void kernel_launch(void* const* d_in, const int* in_sizes, int n_in,
                              void* d_out, int out_size) {
    const float* x   = (const float*)d_in[0];
    const int*   ei  = (const int*)d_in[1];
    const float* W1  = (const float*)d_in[2];
    const float* b1  = (const float*)d_in[3];
    const float* W2  = (const float*)d_in[4];
    const float* b2  = (const float*)d_in[5];
    float*       out = (float*)d_out;

    int n = in_sizes[0] / D_IN;
    int E = in_sizes[1] / 2;
    const int* src = ei;
    const int* dst = ei + E;

    int nb = (n + SCAN_BLK - 1) / SCAN_BLK;
    int n4 = (n + 3) / 4;
    int e4 = (E + 3) / 4;

    k_zero    <<<(n4 + 255) / 256, 256>>>(n4);
    k_count   <<<(e4 + 255) / 256, 256>>>(dst, E);
    k_scanoff <<<nb, 256>>>(n);
    k_fill    <<<(E + 255) / 256, 256>>>(src, dst, E);
    k_gemm1   <<<GEMM_BLOCKS, 256>>>(x, W1, n, GEMM_BLOCKS);
    k_gather1 <<<(n * 32 + 255) / 256, 256>>>(b1, W2, b2, out, n);
    k_gather2 <<<(n * 32 + 255) / 256, 256>>>(out, n);
}